// round 3
// baseline (speedup 1.0000x reference)
#include <cuda_runtime.h>
#include <math.h>
#include <stdint.h>

// ---- static configuration ----
#define NXI 256
#define NYI 256
#define NS  128
// sigma in mm: TIME_RES*0.3/2/2.355 = 300*0.3/2/2.355
#define SIGMA_MM 19.10828025477707f
// tof sigma in pixels: SIGMA_MM / DX
// FILT_C = (pi * tof_sigma_pix)^2
#define FILT_C ((float)(9.554140127388535 * 3.14159265358979323846 * \
                        9.554140127388535 * 3.14159265358979323846))

// ---- scratch buffers (device globals: no allocation allowed) ----
__device__ float  g_img[NYI * NXI];
__device__ float2 g_bufA[NYI * NXI];
__device__ float2 g_bufB[NYI * NXI];

// ================= zero the accumulator image =================
__global__ void zero_img_kernel() {
    int i = blockIdx.x * blockDim.x + threadIdx.x;
    g_img[i] = 0.0f;
}

// ================= TOF backprojection =================
// One warp per event; lanes cover samples inside the +-7 sigma window.
__global__ void bp_kernel(const float* __restrict__ proj,
                          const float* __restrict__ tof,
                          const float* __restrict__ x1l, const float* __restrict__ y1l,
                          const float* __restrict__ x1r, const float* __restrict__ y1r,
                          const float* __restrict__ x2l, const float* __restrict__ y2l,
                          const float* __restrict__ x2r, const float* __restrict__ y2r,
                          int E) {
    int warp = blockIdx.x * (blockDim.x >> 5) + (threadIdx.x >> 5);
    int lane = threadIdx.x & 31;
    if (warp >= E) return;
    const int e = warp;

    const float X1 = 0.5f * (x1l[e] + x1r[e]);
    const float Y1 = 0.5f * (y1l[e] + y1r[e]);
    const float X2 = 0.5f * (x2l[e] + x2r[e]);
    const float Y2 = 0.5f * (y2l[e] + y2r[e]);
    const float ddx = X2 - X1, ddy = Y2 - Y1;
    const float L = sqrtf(ddx * ddx + ddy * ddy);
    const float center = 0.5f * L + tof[e] * 0.15f;       // tof*0.3/2
    const float amp = proj[e] * L * (1.0f / (float)NS);   // proj * L/NS
    const float inv_sigma = 1.0f / SIGMA_MM;
    const float invL = 1.0f / L;

    // sample window: |z| <= 7 -> s in [center-7s, center+7s]
    const float tlo = (center - 7.0f * SIGMA_MM) * invL;
    const float thi = (center + 7.0f * SIGMA_MM) * invL;
    int klo = (int)ceilf(tlo * (float)NS - 0.5f);
    int khi = (int)floorf(thi * (float)NS - 0.5f);
    if (klo < 0) klo = 0;
    if (khi > NS - 1) khi = NS - 1;

    for (int k = klo + lane; k <= khi; k += 32) {
        float t = ((float)k + 0.5f) * (1.0f / (float)NS);
        float z = (t * L - center) * inv_sigma;
        // match reference (unfused mul+add) on the index path
        float px = __fadd_rn(X1, __fmul_rn(t, ddx));
        float py = __fadd_rn(Y1, __fmul_rn(t, ddy));
        int ix = (int)floorf(__fadd_rn(__fmul_rn(px, 0.5f), 128.0f));
        int iy = (int)floorf(__fadd_rn(__fmul_rn(py, 0.5f), 128.0f));
        if ((unsigned)ix < 256u && (unsigned)iy < 256u) {
            float w = __expf(-0.5f * z * z) * amp;
            atomicAdd(&g_img[iy * NXI + ix], w);
        }
    }
}

// ================= shared-memory radix-2 FFT, N=256 =================
// 128 threads per block. dir = -1 forward, +1 inverse (sign of exponent).
__device__ __forceinline__ int brev8(int i) {
    return (int)(__brev((unsigned)i) >> 24);
}

__device__ __forceinline__ void fft256(float2* sm, int tid, float dir) {
    #pragma unroll
    for (int half = 1; half < 256; half <<= 1) {
        __syncthreads();
        int j = tid & (half - 1);
        int base = ((tid & ~(half - 1)) << 1) + j;
        float ang = dir * 3.14159265358979323846f * (float)j / (float)half;
        float sn, cs;
        sincosf(ang, &sn, &cs);
        float2 a = sm[base];
        float2 b = sm[base + half];
        float tr = b.x * cs - b.y * sn;
        float ti = b.x * sn + b.y * cs;
        sm[base]        = make_float2(a.x + tr, a.y + ti);
        sm[base + half] = make_float2(a.x - tr, a.y - ti);
    }
    __syncthreads();
}

// forward FFT over rows; input: g_img / 4 (the /DX/DY normalization)
__global__ void fft_rows_fwd_kernel() {
    __shared__ float2 s[256];
    int y = blockIdx.x, tid = threadIdx.x;
    s[brev8(tid)]       = make_float2(g_img[y * NXI + tid] * 0.25f, 0.0f);
    s[brev8(tid + 128)] = make_float2(g_img[y * NXI + tid + 128] * 0.25f, 0.0f);
    fft256(s, tid, -1.0f);
    g_bufA[y * NXI + tid]       = s[tid];
    g_bufA[y * NXI + tid + 128] = s[tid + 128];
}

// i0e(x) = exp(-x) * I0(x), Abramowitz-Stegun 9.8.1 / 9.8.2 (rel err ~2e-7)
__device__ __forceinline__ float i0e_f(float x) {
    if (x < 3.75f) {
        float t = x * (1.0f / 3.75f);
        t *= t;
        float I0 = 1.0f + t * (3.5156229f + t * (3.0899424f + t * (1.2067492f +
                   t * (0.2659732f + t * (0.0360768f + t * 0.0045813f)))));
        return I0 * expf(-x);
    } else {
        float t = 3.75f / x;
        float p = 0.39894228f + t * (0.01328592f + t * (0.00225319f +
                  t * (-0.00157565f + t * (0.00916281f + t * (-0.02057706f +
                  t * (0.02635537f + t * (-0.01647633f + t * 0.00392377f)))))));
        return p * rsqrtf(x);
    }
}

// shifted-grid frequency coordinate for FFT index k:
// p = (k+128)&255, u = (p - 127.5)/128
__device__ __forceinline__ float ufreq(int k) {
    float u = ((float)k + 0.5f) * (1.0f / 128.0f);
    return (k < 128) ? u : (u - 2.0f);
}

// forward FFT over cols + filter multiply + combined scale NX/(NX*NY) = 1/256
__global__ void fft_cols_fwd_filter_kernel() {
    __shared__ float2 s[256];
    int x = blockIdx.x, tid = threadIdx.x;
    s[brev8(tid)]       = g_bufA[tid * NXI + x];
    s[brev8(tid + 128)] = g_bufA[(tid + 128) * NXI + x];
    fft256(s, tid, -1.0f);
    float ux = ufreq(x);
    float cx = ux * ux;
    #pragma unroll
    for (int r = tid; r < 256; r += 128) {
        float uy = ufreq(r);
        float tmp = FILT_C * (uy * uy + cx);
        float f = (1.0f / 256.0f) / i0e_f(tmp);
        float2 v = s[r];
        g_bufB[r * NXI + x] = make_float2(v.x * f, v.y * f);
    }
}

// inverse FFT over cols (scaling already folded in)
__global__ void fft_cols_inv_kernel() {
    __shared__ float2 s[256];
    int x = blockIdx.x, tid = threadIdx.x;
    s[brev8(tid)]       = g_bufB[tid * NXI + x];
    s[brev8(tid + 128)] = g_bufB[(tid + 128) * NXI + x];
    fft256(s, tid, 1.0f);
    g_bufA[tid * NXI + x]         = s[tid];
    g_bufA[(tid + 128) * NXI + x] = s[tid + 128];
}

// inverse FFT over rows, write real part to output
__global__ void fft_rows_inv_kernel(float* __restrict__ out) {
    __shared__ float2 s[256];
    int y = blockIdx.x, tid = threadIdx.x;
    s[brev8(tid)]       = g_bufA[y * NXI + tid];
    s[brev8(tid + 128)] = g_bufA[y * NXI + tid + 128];
    fft256(s, tid, 1.0f);
    out[y * NXI + tid]       = s[tid].x;
    out[y * NXI + tid + 128] = s[tid + 128].x;
}

extern "C" void kernel_launch(void* const* d_in, const int* in_sizes, int n_in,
                              void* d_out, int out_size) {
    const float* proj = (const float*)d_in[0];
    const float* tof  = (const float*)d_in[1];
    const float* x1l  = (const float*)d_in[2];
    const float* y1l  = (const float*)d_in[3];
    const float* x1r  = (const float*)d_in[4];
    const float* y1r  = (const float*)d_in[5];
    const float* x2l  = (const float*)d_in[6];
    const float* y2l  = (const float*)d_in[7];
    const float* x2r  = (const float*)d_in[8];
    const float* y2r  = (const float*)d_in[9];
    int E = in_sizes[0];

    zero_img_kernel<<<64, 1024>>>();

    int warpsPerBlock = 8;
    int blocks = (E + warpsPerBlock - 1) / warpsPerBlock;
    bp_kernel<<<blocks, warpsPerBlock * 32>>>(proj, tof, x1l, y1l, x1r, y1r,
                                              x2l, y2l, x2r, y2r, E);

    fft_rows_fwd_kernel<<<256, 128>>>();
    fft_cols_fwd_filter_kernel<<<256, 128>>>();
    fft_cols_inv_kernel<<<256, 128>>>();
    fft_rows_inv_kernel<<<256, 128>>>((float*)d_out);
}